// round 1
// baseline (speedup 1.0000x reference)
#include <cuda_runtime.h>
#include <cstdint>

#define NB 64
#define TB 1024
#define IB 88
#define HB 1024

#define NCTA 128
#define JB 8            // output columns per CTA (128*8 = 1024)
#define KC 256          // k chunk staged in smem
#define NCHUNK (HB / KC)
#define RT 256          // threads in recurrence kernel (8 warps)

static_assert(NCTA * JB == HB, "partition");

// ---------------- device scratch (no allocations allowed) ----------------
__device__ __align__(256) float g_ih[(size_t)NB * TB * HB];   // 256 MB: ih[n][t][h]
__device__ __align__(256) float g_h[2][HB][NB];               // ping-pong h, k-major [k][n]
__device__ unsigned g_flags[NCTA];                            // barrier flags

__global__ void init_kernel() {
    if (threadIdx.x < NCTA) g_flags[threadIdx.x] = 0u;
}

// ---------------- cp.async helpers ----------------
__device__ __forceinline__ void cpasync16(void* dst_smem, const void* src) {
    unsigned d = (unsigned)__cvta_generic_to_shared(dst_smem);
    asm volatile("cp.async.cg.shared.global [%0], [%1], 16;\n" ::"r"(d), "l"(src));
}
__device__ __forceinline__ void cpasync_commit() {
    asm volatile("cp.async.commit_group;\n");
}
template <int NGroups>
__device__ __forceinline__ void cpasync_wait() {
    asm volatile("cp.async.wait_group %0;\n" ::"n"(NGroups));
}

// ---------------- kernel 1: ih[n][t][h] = sum_i x[n][t][i]*W_ih[h][i] + b[h] ------
// grid: (HB/128, NB*TB/64), 256 threads. CTA tile: 64 rows (m=n*T+t) x 128 cols.
__global__ __launch_bounds__(256) void ih_kernel(const float* __restrict__ x,
                                                 const float* __restrict__ W_ih,
                                                 const float* __restrict__ b_ih) {
    extern __shared__ float sm[];
    float* xs = sm;            // [IB][64]  transposed x tile
    float* wt = sm + IB * 64;  // [IB][128] transposed W tile
    const int jb = blockIdx.x * 128;
    const int mb = blockIdx.y * 64;
    const int tid = threadIdx.x;

    for (int e = tid; e < 64 * IB; e += 256) {
        int m = e / IB, i = e - m * IB;
        xs[i * 64 + m] = x[(size_t)(mb + m) * IB + i];
    }
    for (int e = tid; e < 128 * IB; e += 256) {
        int j = e / IB, i = e - j * IB;
        wt[i * 128 + j] = W_ih[(size_t)(jb + j) * IB + i];
    }
    __syncthreads();

    const int jo = (tid & 15) * 8;   // 16 j-octets
    const int mo = (tid >> 4) * 4;   // 16 m-quads
    float acc[4][8];
#pragma unroll
    for (int jj = 0; jj < 8; jj++) {
        float b = b_ih[jb + jo + jj];
        acc[0][jj] = b; acc[1][jj] = b; acc[2][jj] = b; acc[3][jj] = b;
    }
#pragma unroll 4
    for (int i = 0; i < IB; i++) {
        float4 xv = *(const float4*)&xs[i * 64 + mo];
        float4 w0 = *(const float4*)&wt[i * 128 + jo];
        float4 w1 = *(const float4*)&wt[i * 128 + jo + 4];
        float xm[4] = {xv.x, xv.y, xv.z, xv.w};
#pragma unroll
        for (int mm = 0; mm < 4; mm++) {
            acc[mm][0] += xm[mm] * w0.x;
            acc[mm][1] += xm[mm] * w0.y;
            acc[mm][2] += xm[mm] * w0.z;
            acc[mm][3] += xm[mm] * w0.w;
            acc[mm][4] += xm[mm] * w1.x;
            acc[mm][5] += xm[mm] * w1.y;
            acc[mm][6] += xm[mm] * w1.z;
            acc[mm][7] += xm[mm] * w1.w;
        }
    }
#pragma unroll
    for (int mm = 0; mm < 4; mm++) {
        size_t row = (size_t)(mb + mo + mm) * HB + jb + jo;
        *(float4*)&g_ih[row]     = make_float4(acc[mm][0], acc[mm][1], acc[mm][2], acc[mm][3]);
        *(float4*)&g_ih[row + 4] = make_float4(acc[mm][4], acc[mm][5], acc[mm][6], acc[mm][7]);
    }
}

// ---------------- persistent recurrence kernel ----------------
// 128 CTAs (all co-resident: occupancy 1, 128 <= 148 SMs), each owns JB=8 output cols.
// W slice (transposed, [1024][8]) resident in SMEM for the whole kernel.
// h ping-pongs between g_h[0]/g_h[1] in k-major [k][n] layout so chunks are contiguous.
__device__ __forceinline__ void grid_barrier(unsigned target, int bid, int tid) {
    __threadfence();
    __syncthreads();
    if (tid == 0) *(volatile unsigned*)&g_flags[bid] = target;
    bool ok;
    do {
        ok = true;
        if (tid < NCTA) ok = (*(volatile unsigned*)&g_flags[tid] >= target);
    } while (!__syncthreads_and((int)ok));
    __threadfence();
}

__global__ __launch_bounds__(RT) void rnn_kernel(const float* __restrict__ initial,
                                                 const float* __restrict__ W_hh,
                                                 float* __restrict__ out, int two) {
    extern __shared__ float sm[];
    float* ws = sm;                 // [HB][JB]  W slice transposed: ws[k][j]
    float* hs = sm + HB * JB;       // [2][KC][NB] double-buffered h chunk
    float* red = hs;                // alias: reduction buffer lives in buf0 (last chunk uses buf1)

    const int bid = blockIdx.x;
    const int tid = threadIdx.x;
    const int warp = tid >> 5;
    const int lane = tid & 31;
    const int jbase = bid * JB;

    // stage W slice (once): ws[k][j] = W_hh[jbase+j][k]
    for (int e = tid; e < JB * HB; e += RT) {
        int j = e >> 10, k = e & (HB - 1);
        ws[k * JB + j] = W_hh[(size_t)(jbase + j) * HB + k];
    }

    // per-thread compute tile: lane -> (nq, jh); 4n x 4j, warp covers 32-k subrange
    const int nq = lane >> 1;          // 0..15
    const int jh = lane & 1;           // 0..1
    const int n0 = nq * 4;
    const int j0 = jh * 4;
    const int kw = warp * 32;          // k offset inside chunk

    // per-thread epilogue mapping (t-invariant): two outputs
    int o_n[2], o_j[2];
    size_t o_base[2];
#pragma unroll
    for (int r = 0; r < 2; r++) {
        int o = ((tid & 31) << 4) | (r << 3) | (tid >> 5);
        int lane_o = o >> 4, idx_o = o & 15;
        int n = (lane_o >> 1) * 4 + (idx_o >> 2);
        int j = (lane_o & 1) * 4 + (idx_o & 3);
        o_n[r] = n;
        o_j[r] = j;
        o_base[r] = (size_t)n * TB * HB + jbase + j;
    }
    const size_t NTH = (size_t)NB * TB * HB;

    // ---- step 0: h0 = initial + ih[:,0]
    for (int o = tid; o < NB * JB; o += RT) {
        int n = o & (NB - 1);
        int j = o >> 6;
        float v = initial[(size_t)n * HB + jbase + j] + g_ih[(size_t)n * TB * HB + jbase + j];
        g_h[0][jbase + j][n] = v;
        out[(size_t)n * TB * HB + jbase + j] = v;
        if (two) out[NTH + (size_t)n * TB * HB + jbase + j] = v;
    }
    grid_barrier(1u, bid, tid);

    // ---- steps 1..T-1
    for (int t = 1; t < TB; t++) {
        const float* hOld = &g_h[(t - 1) & 1][0][0];
        float* hNewCol = &g_h[t & 1][0][0];

        // prefetch u values early (latency hidden under the GEMM)
        float u0 = g_ih[o_base[0] + (size_t)(t - 1) * HB];
        float u1 = g_ih[o_base[1] + (size_t)(t - 1) * HB];

        // prefetch chunk 0
        {
            float* dst = hs;
            const float* src = hOld;
#pragma unroll
            for (int i = 0; i < (KC * NB / 4) / RT; i++) {
                int idx = tid + i * RT;
                cpasync16(dst + idx * 4, src + idx * 4);
            }
            cpasync_commit();
        }

        float a[16];
#pragma unroll
        for (int i = 0; i < 16; i++) a[i] = 0.f;

        for (int c = 0; c < NCHUNK; c++) {
            if (c + 1 < NCHUNK) {
                float* dst = hs + ((c + 1) & 1) * KC * NB;
                const float* src = hOld + (size_t)(c + 1) * KC * NB;
#pragma unroll
                for (int i = 0; i < (KC * NB / 4) / RT; i++) {
                    int idx = tid + i * RT;
                    cpasync16(dst + idx * 4, src + idx * 4);
                }
                cpasync_commit();
                cpasync_wait<1>();   // chunk c complete
            } else {
                cpasync_wait<0>();
            }
            __syncthreads();   // chunk c visible to everyone; safe to compute

            const float* hp = hs + (c & 1) * KC * NB + kw * NB;
            const float* wp = ws + (c * KC + kw) * JB;
#pragma unroll 8
            for (int k = 0; k < 32; k++) {
                float4 hv = *(const float4*)(hp + k * NB + n0);
                float4 wv = *(const float4*)(wp + k * JB + j0);
                a[0]  += hv.x * wv.x;  a[1]  += hv.x * wv.y;
                a[2]  += hv.x * wv.z;  a[3]  += hv.x * wv.w;
                a[4]  += hv.y * wv.x;  a[5]  += hv.y * wv.y;
                a[6]  += hv.y * wv.z;  a[7]  += hv.y * wv.w;
                a[8]  += hv.z * wv.x;  a[9]  += hv.z * wv.y;
                a[10] += hv.z * wv.z;  a[11] += hv.z * wv.w;
                a[12] += hv.w * wv.x;  a[13] += hv.w * wv.y;
                a[14] += hv.w * wv.z;  a[15] += hv.w * wv.w;
            }
            __syncthreads();   // done reading buf[c&1] before it is restaged next iter
        }

        // reduce 8 warp-partials per output (red aliases buf0; last compute used buf1)
#pragma unroll
        for (int idx = 0; idx < 16; idx++) red[warp * 512 + idx * 32 + lane] = a[idx];
        __syncthreads();

#pragma unroll
        for (int r = 0; r < 2; r++) {
            int o = ((tid & 31) << 4) | (r << 3) | (tid >> 5);
            int lane_o = o >> 4, idx_o = o & 15;
            float s = 0.f;
#pragma unroll
            for (int w = 0; w < 8; w++) s += red[w * 512 + idx_o * 32 + lane_o];
            float v = s + (r == 0 ? u0 : u1);
            hNewCol[(jbase + o_j[r]) * NB + o_n[r]] = v;
            size_t oaddr = o_base[r] + (size_t)t * HB;
            out[oaddr] = v;
            if (two) out[NTH + oaddr] = v;
        }

        if (t < TB - 1) grid_barrier((unsigned)(t + 1), bid, tid);
    }
}

// ---------------- launch ----------------
extern "C" void kernel_launch(void* const* d_in, const int* in_sizes, int n_in,
                              void* d_out, int out_size) {
    // defensive: map inputs by unique element counts
    const float* x = nullptr;        // 64*1024*88   = 5767168
    const float* initial = nullptr;  // 64*1024      = 65536
    const float* W_ih = nullptr;     // 1024*88      = 90112
    const float* b_ih = nullptr;     // 1024
    const float* W_hh = nullptr;     // 1024*1024    = 1048576
    for (int i = 0; i < n_in; i++) {
        switch (in_sizes[i]) {
            case 5767168: x = (const float*)d_in[i]; break;
            case 65536:   initial = (const float*)d_in[i]; break;
            case 90112:   W_ih = (const float*)d_in[i]; break;
            case 1024:    b_ih = (const float*)d_in[i]; break;
            case 1048576: W_hh = (const float*)d_in[i]; break;
            default: break;
        }
    }
    float* out = (float*)d_out;
    const long long NTH = (long long)NB * TB * HB;
    int two = ((long long)out_size >= 2 * NTH) ? 1 : 0;

    const int IH_SMEM = (IB * 64 + IB * 128) * 4;          // 67,584 B
    const int RNN_SMEM = (HB * JB + 2 * KC * NB) * 4;      // 163,840 B
    cudaFuncSetAttribute(ih_kernel, cudaFuncAttributeMaxDynamicSharedMemorySize, IH_SMEM);
    cudaFuncSetAttribute(rnn_kernel, cudaFuncAttributeMaxDynamicSharedMemorySize, RNN_SMEM);

    init_kernel<<<1, 128>>>();
    dim3 g1(HB / 128, (NB * TB) / 64);
    ih_kernel<<<g1, 256, IH_SMEM>>>(x, W_ih, b_ih);
    rnn_kernel<<<NCTA, RT, RNN_SMEM>>>(initial, W_hh, out, two);
}

// round 2
// speedup vs baseline: 1.0262x; 1.0262x over previous
#include <cuda_runtime.h>
#include <cstdint>

#define NB 64
#define TB 1024
#define IB 88
#define HB 1024

#define NCTA 128
#define JB 8            // output columns per CTA (128*8 = 1024)
#define KC 256          // k chunk staged in smem
#define NCHUNK (HB / KC)
#define RT 256          // threads in recurrence kernel (8 warps)

static_assert(NCTA * JB == HB, "partition");

// ---------------- device scratch (no allocations allowed) ----------------
__device__ __align__(256) float g_ih[(size_t)NB * TB * HB];   // 256 MB: ih[n][t][h]
__device__ __align__(256) float g_h[2][HB][NB];               // ping-pong h, k-major [k][n]
__device__ unsigned g_flags[NCTA];                            // barrier flags

__global__ void init_kernel() {
    if (threadIdx.x < NCTA) g_flags[threadIdx.x] = 0u;
}

// ---------------- cp.async helpers ----------------
__device__ __forceinline__ void cpasync16(void* dst_smem, const void* src) {
    unsigned d = (unsigned)__cvta_generic_to_shared(dst_smem);
    asm volatile("cp.async.cg.shared.global [%0], [%1], 16;\n" ::"r"(d), "l"(src));
}
__device__ __forceinline__ void cpasync_commit() {
    asm volatile("cp.async.commit_group;\n");
}
template <int NGroups>
__device__ __forceinline__ void cpasync_wait() {
    asm volatile("cp.async.wait_group %0;\n" ::"n"(NGroups));
}

// ---------------- kernel 1: ih[n][t][h] = sum_i x[n][t][i]*W_ih[h][i] + b[h] ------
// grid: (HB/128, NB*TB/64), 256 threads. CTA tile: 64 rows (m=n*T+t) x 128 cols.
__global__ __launch_bounds__(256) void ih_kernel(const float* __restrict__ x,
                                                 const float* __restrict__ W_ih,
                                                 const float* __restrict__ b_ih) {
    extern __shared__ float sm[];
    float* xs = sm;            // [IB][64]  transposed x tile
    float* wt = sm + IB * 64;  // [IB][128] transposed W tile
    const int jb = blockIdx.x * 128;
    const int mb = blockIdx.y * 64;
    const int tid = threadIdx.x;

    for (int e = tid; e < 64 * IB; e += 256) {
        int m = e / IB, i = e - m * IB;
        xs[i * 64 + m] = x[(size_t)(mb + m) * IB + i];
    }
    for (int e = tid; e < 128 * IB; e += 256) {
        int j = e / IB, i = e - j * IB;
        wt[i * 128 + j] = W_ih[(size_t)(jb + j) * IB + i];
    }
    __syncthreads();

    const int jo = (tid & 15) * 8;   // 16 j-octets
    const int mo = (tid >> 4) * 4;   // 16 m-quads
    float acc[4][8];
#pragma unroll
    for (int jj = 0; jj < 8; jj++) {
        float b = b_ih[jb + jo + jj];
        acc[0][jj] = b; acc[1][jj] = b; acc[2][jj] = b; acc[3][jj] = b;
    }
#pragma unroll 4
    for (int i = 0; i < IB; i++) {
        float4 xv = *(const float4*)&xs[i * 64 + mo];
        float4 w0 = *(const float4*)&wt[i * 128 + jo];
        float4 w1 = *(const float4*)&wt[i * 128 + jo + 4];
        float xm[4] = {xv.x, xv.y, xv.z, xv.w};
#pragma unroll
        for (int mm = 0; mm < 4; mm++) {
            acc[mm][0] += xm[mm] * w0.x;
            acc[mm][1] += xm[mm] * w0.y;
            acc[mm][2] += xm[mm] * w0.z;
            acc[mm][3] += xm[mm] * w0.w;
            acc[mm][4] += xm[mm] * w1.x;
            acc[mm][5] += xm[mm] * w1.y;
            acc[mm][6] += xm[mm] * w1.z;
            acc[mm][7] += xm[mm] * w1.w;
        }
    }
#pragma unroll
    for (int mm = 0; mm < 4; mm++) {
        size_t row = (size_t)(mb + mo + mm) * HB + jb + jo;
        *(float4*)&g_ih[row]     = make_float4(acc[mm][0], acc[mm][1], acc[mm][2], acc[mm][3]);
        *(float4*)&g_ih[row + 4] = make_float4(acc[mm][4], acc[mm][5], acc[mm][6], acc[mm][7]);
    }
}

// ---------------- persistent recurrence kernel ----------------
// 128 CTAs (all co-resident: occupancy 1, 128 <= 148 SMs), each owns JB=8 output cols.
// W slice (transposed, [1024][8]) resident in SMEM for the whole kernel.
// h ping-pongs between g_h[0]/g_h[1] in k-major [k][n] layout so chunks are contiguous.
__device__ __forceinline__ void grid_barrier(unsigned target, int bid, int tid) {
    __threadfence();
    __syncthreads();
    if (tid == 0) *(volatile unsigned*)&g_flags[bid] = target;
    bool ok;
    do {
        ok = true;
        if (tid < NCTA) ok = (*(volatile unsigned*)&g_flags[tid] >= target);
    } while (!__syncthreads_and((int)ok));
    __threadfence();
}

__global__ __launch_bounds__(RT) void rnn_kernel(const float* __restrict__ initial,
                                                 const float* __restrict__ W_hh,
                                                 float* __restrict__ out, int two) {
    extern __shared__ float sm[];
    float* ws = sm;                 // [HB][JB]  W slice transposed: ws[k][j]
    float* hs = sm + HB * JB;       // [2][KC][NB] double-buffered h chunk
    float* red = hs;                // alias: reduction buffer lives in buf0 (last chunk uses buf1)

    const int bid = blockIdx.x;
    const int tid = threadIdx.x;
    const int warp = tid >> 5;
    const int lane = tid & 31;
    const int jbase = bid * JB;

    // stage W slice (once): ws[k][j] = W_hh[jbase+j][k]
    for (int e = tid; e < JB * HB; e += RT) {
        int j = e >> 10, k = e & (HB - 1);
        ws[k * JB + j] = W_hh[(size_t)(jbase + j) * HB + k];
    }

    // per-thread compute tile: lane -> (nq, jh); 4n x 4j, warp covers 32-k subrange
    const int nq = lane >> 1;          // 0..15
    const int jh = lane & 1;           // 0..1
    const int n0 = nq * 4;
    const int j0 = jh * 4;
    const int kw = warp * 32;          // k offset inside chunk

    // per-thread epilogue mapping (t-invariant): two outputs
    int o_n[2], o_j[2];
    size_t o_base[2];
#pragma unroll
    for (int r = 0; r < 2; r++) {
        int o = ((tid & 31) << 4) | (r << 3) | (tid >> 5);
        int lane_o = o >> 4, idx_o = o & 15;
        int n = (lane_o >> 1) * 4 + (idx_o >> 2);
        int j = (lane_o & 1) * 4 + (idx_o & 3);
        o_n[r] = n;
        o_j[r] = j;
        o_base[r] = (size_t)n * TB * HB + jbase + j;
    }
    const size_t NTH = (size_t)NB * TB * HB;

    // ---- step 0: h0 = initial + ih[:,0]
    for (int o = tid; o < NB * JB; o += RT) {
        int n = o & (NB - 1);
        int j = o >> 6;
        float v = initial[(size_t)n * HB + jbase + j] + g_ih[(size_t)n * TB * HB + jbase + j];
        g_h[0][jbase + j][n] = v;
        out[(size_t)n * TB * HB + jbase + j] = v;
        if (two) out[NTH + (size_t)n * TB * HB + jbase + j] = v;
    }
    grid_barrier(1u, bid, tid);

    // ---- steps 1..T-1
    for (int t = 1; t < TB; t++) {
        const float* hOld = &g_h[(t - 1) & 1][0][0];
        float* hNewCol = &g_h[t & 1][0][0];

        // prefetch u values early (latency hidden under the GEMM)
        float u0 = g_ih[o_base[0] + (size_t)(t - 1) * HB];
        float u1 = g_ih[o_base[1] + (size_t)(t - 1) * HB];

        // prefetch chunk 0
        {
            float* dst = hs;
            const float* src = hOld;
#pragma unroll
            for (int i = 0; i < (KC * NB / 4) / RT; i++) {
                int idx = tid + i * RT;
                cpasync16(dst + idx * 4, src + idx * 4);
            }
            cpasync_commit();
        }

        float a[16];
#pragma unroll
        for (int i = 0; i < 16; i++) a[i] = 0.f;

        for (int c = 0; c < NCHUNK; c++) {
            if (c + 1 < NCHUNK) {
                float* dst = hs + ((c + 1) & 1) * KC * NB;
                const float* src = hOld + (size_t)(c + 1) * KC * NB;
#pragma unroll
                for (int i = 0; i < (KC * NB / 4) / RT; i++) {
                    int idx = tid + i * RT;
                    cpasync16(dst + idx * 4, src + idx * 4);
                }
                cpasync_commit();
                cpasync_wait<1>();   // chunk c complete
            } else {
                cpasync_wait<0>();
            }
            __syncthreads();   // chunk c visible to everyone; safe to compute

            const float* hp = hs + (c & 1) * KC * NB + kw * NB;
            const float* wp = ws + (c * KC + kw) * JB;
#pragma unroll 8
            for (int k = 0; k < 32; k++) {
                float4 hv = *(const float4*)(hp + k * NB + n0);
                float4 wv = *(const float4*)(wp + k * JB + j0);
                a[0]  += hv.x * wv.x;  a[1]  += hv.x * wv.y;
                a[2]  += hv.x * wv.z;  a[3]  += hv.x * wv.w;
                a[4]  += hv.y * wv.x;  a[5]  += hv.y * wv.y;
                a[6]  += hv.y * wv.z;  a[7]  += hv.y * wv.w;
                a[8]  += hv.z * wv.x;  a[9]  += hv.z * wv.y;
                a[10] += hv.z * wv.z;  a[11] += hv.z * wv.w;
                a[12] += hv.w * wv.x;  a[13] += hv.w * wv.y;
                a[14] += hv.w * wv.z;  a[15] += hv.w * wv.w;
            }
            __syncthreads();   // done reading buf[c&1] before it is restaged next iter
        }

        // reduce 8 warp-partials per output (red aliases buf0; last compute used buf1)
#pragma unroll
        for (int idx = 0; idx < 16; idx++) red[warp * 512 + idx * 32 + lane] = a[idx];
        __syncthreads();

#pragma unroll
        for (int r = 0; r < 2; r++) {
            int o = ((tid & 31) << 4) | (r << 3) | (tid >> 5);
            int lane_o = o >> 4, idx_o = o & 15;
            float s = 0.f;
#pragma unroll
            for (int w = 0; w < 8; w++) s += red[w * 512 + idx_o * 32 + lane_o];
            float v = s + (r == 0 ? u0 : u1);
            hNewCol[(jbase + o_j[r]) * NB + o_n[r]] = v;
            size_t oaddr = o_base[r] + (size_t)t * HB;
            out[oaddr] = v;
            if (two) out[NTH + oaddr] = v;
        }

        if (t < TB - 1) grid_barrier((unsigned)(t + 1), bid, tid);
    }
}

// ---------------- launch ----------------
extern "C" void kernel_launch(void* const* d_in, const int* in_sizes, int n_in,
                              void* d_out, int out_size) {
    // defensive: map inputs by unique element counts
    const float* x = nullptr;        // 64*1024*88   = 5767168
    const float* initial = nullptr;  // 64*1024      = 65536
    const float* W_ih = nullptr;     // 1024*88      = 90112
    const float* b_ih = nullptr;     // 1024
    const float* W_hh = nullptr;     // 1024*1024    = 1048576
    for (int i = 0; i < n_in; i++) {
        switch (in_sizes[i]) {
            case 5767168: x = (const float*)d_in[i]; break;
            case 65536:   initial = (const float*)d_in[i]; break;
            case 90112:   W_ih = (const float*)d_in[i]; break;
            case 1024:    b_ih = (const float*)d_in[i]; break;
            case 1048576: W_hh = (const float*)d_in[i]; break;
            default: break;
        }
    }
    float* out = (float*)d_out;
    const long long NTH = (long long)NB * TB * HB;
    int two = ((long long)out_size >= 2 * NTH) ? 1 : 0;

    const int IH_SMEM = (IB * 64 + IB * 128) * 4;          // 67,584 B
    const int RNN_SMEM = (HB * JB + 2 * KC * NB) * 4;      // 163,840 B
    cudaFuncSetAttribute(ih_kernel, cudaFuncAttributeMaxDynamicSharedMemorySize, IH_SMEM);
    cudaFuncSetAttribute(rnn_kernel, cudaFuncAttributeMaxDynamicSharedMemorySize, RNN_SMEM);

    init_kernel<<<1, 128>>>();
    dim3 g1(HB / 128, (NB * TB) / 64);
    ih_kernel<<<g1, 256, IH_SMEM>>>(x, W_ih, b_ih);
    rnn_kernel<<<NCTA, RT, RNN_SMEM>>>(initial, W_hh, out, two);
}

// round 3
// speedup vs baseline: 1.2045x; 1.1738x over previous
#include <cuda_runtime.h>
#include <cstdint>

#define NB 64
#define TB 1024
#define IB 88
#define HB 1024

#define NCTA 128
#define JB 8            // output columns per CTA (128*8 = 1024)
#define KC 256          // k chunk staged in smem
#define NCHUNK (HB / KC)
#define RT 256          // threads in recurrence kernel (8 warps)

static_assert(NCTA * JB == HB, "partition");

// ---------------- device scratch (no allocations allowed) ----------------
__device__ __align__(256) float g_ih[(size_t)NB * TB * HB];   // 256 MB: ih[n][t][h]
__device__ __align__(256) float g_h[2][HB][NB];               // ping-pong h, k-major [k][n]
__device__ unsigned g_flags[NCTA];                            // barrier flags

__global__ void init_kernel() {
    if (threadIdx.x < NCTA) g_flags[threadIdx.x] = 0u;
}

// ---------------- cp.async helpers ----------------
__device__ __forceinline__ void cpasync16(void* dst_smem, const void* src) {
    unsigned d = (unsigned)__cvta_generic_to_shared(dst_smem);
    asm volatile("cp.async.cg.shared.global [%0], [%1], 16;\n" ::"r"(d), "l"(src));
}
__device__ __forceinline__ void cpasync_commit() {
    asm volatile("cp.async.commit_group;\n");
}
template <int NGroups>
__device__ __forceinline__ void cpasync_wait() {
    asm volatile("cp.async.wait_group %0;\n" ::"n"(NGroups));
}

// ---------------- kernel 1: ih[n][t][h] = sum_i x[n][t][i]*W_ih[h][i] + b[h] ------
// grid: (HB/128, NB*TB/64), 256 threads. CTA tile: 64 rows (m=n*T+t) x 128 cols.
__global__ __launch_bounds__(256) void ih_kernel(const float* __restrict__ x,
                                                 const float* __restrict__ W_ih,
                                                 const float* __restrict__ b_ih) {
    extern __shared__ float sm[];
    float* xs = sm;            // [IB][64]  transposed x tile
    float* wt = sm + IB * 64;  // [IB][128] transposed W tile
    const int jb = blockIdx.x * 128;
    const int mb = blockIdx.y * 64;
    const int tid = threadIdx.x;

    for (int e = tid; e < 64 * IB; e += 256) {
        int m = e / IB, i = e - m * IB;
        xs[i * 64 + m] = x[(size_t)(mb + m) * IB + i];
    }
    for (int e = tid; e < 128 * IB; e += 256) {
        int j = e / IB, i = e - j * IB;
        wt[i * 128 + j] = W_ih[(size_t)(jb + j) * IB + i];
    }
    __syncthreads();

    const int jo = (tid & 15) * 8;   // 16 j-octets
    const int mo = (tid >> 4) * 4;   // 16 m-quads
    float acc[4][8];
#pragma unroll
    for (int jj = 0; jj < 8; jj++) {
        float b = b_ih[jb + jo + jj];
        acc[0][jj] = b; acc[1][jj] = b; acc[2][jj] = b; acc[3][jj] = b;
    }
#pragma unroll 4
    for (int i = 0; i < IB; i++) {
        float4 xv = *(const float4*)&xs[i * 64 + mo];
        float4 w0 = *(const float4*)&wt[i * 128 + jo];
        float4 w1 = *(const float4*)&wt[i * 128 + jo + 4];
        float xm[4] = {xv.x, xv.y, xv.z, xv.w};
#pragma unroll
        for (int mm = 0; mm < 4; mm++) {
            acc[mm][0] += xm[mm] * w0.x;
            acc[mm][1] += xm[mm] * w0.y;
            acc[mm][2] += xm[mm] * w0.z;
            acc[mm][3] += xm[mm] * w0.w;
            acc[mm][4] += xm[mm] * w1.x;
            acc[mm][5] += xm[mm] * w1.y;
            acc[mm][6] += xm[mm] * w1.z;
            acc[mm][7] += xm[mm] * w1.w;
        }
    }
#pragma unroll
    for (int mm = 0; mm < 4; mm++) {
        size_t row = (size_t)(mb + mo + mm) * HB + jb + jo;
        *(float4*)&g_ih[row]     = make_float4(acc[mm][0], acc[mm][1], acc[mm][2], acc[mm][3]);
        *(float4*)&g_ih[row + 4] = make_float4(acc[mm][4], acc[mm][5], acc[mm][6], acc[mm][7]);
    }
}

// ---------------- persistent recurrence kernel ----------------
// 128 CTAs (all co-resident: occupancy 1, 128 <= 148 SMs), each owns JB=8 output cols.
// W slice (transposed, [1024][8]) resident in SMEM for the whole kernel.
// h ping-pongs between g_h[0]/g_h[1] in k-major [k][n] layout so chunks are contiguous.
__device__ __forceinline__ void grid_barrier(unsigned target, int bid, int tid) {
    __threadfence();
    __syncthreads();
    if (tid == 0) *(volatile unsigned*)&g_flags[bid] = target;
    bool ok;
    do {
        ok = true;
        if (tid < NCTA) ok = (*(volatile unsigned*)&g_flags[tid] >= target);
    } while (!__syncthreads_and((int)ok));
    __threadfence();
}

__global__ __launch_bounds__(RT) void rnn_kernel(const float* __restrict__ initial,
                                                 const float* __restrict__ W_hh,
                                                 float* __restrict__ out, int two) {
    extern __shared__ float sm[];
    float* ws = sm;                 // [HB][JB]  W slice transposed: ws[k][j]
    float* hs = sm + HB * JB;       // [2][KC][NB] double-buffered h chunk
    float* red = hs;                // alias: reduction buffer lives in buf0 (last chunk uses buf1)

    const int bid = blockIdx.x;
    const int tid = threadIdx.x;
    const int warp = tid >> 5;
    const int lane = tid & 31;
    const int jbase = bid * JB;

    // stage W slice (once): ws[k][j] = W_hh[jbase+j][k]
    for (int e = tid; e < JB * HB; e += RT) {
        int j = e >> 10, k = e & (HB - 1);
        ws[k * JB + j] = W_hh[(size_t)(jbase + j) * HB + k];
    }

    // per-thread compute tile: lane -> (nq, jh); 4n x 4j, warp covers 32-k subrange
    const int nq = lane >> 1;          // 0..15
    const int jh = lane & 1;           // 0..1
    const int n0 = nq * 4;
    const int j0 = jh * 4;
    const int kw = warp * 32;          // k offset inside chunk

    // per-thread epilogue mapping (t-invariant): two outputs
    int o_n[2], o_j[2];
    size_t o_base[2];
#pragma unroll
    for (int r = 0; r < 2; r++) {
        int o = ((tid & 31) << 4) | (r << 3) | (tid >> 5);
        int lane_o = o >> 4, idx_o = o & 15;
        int n = (lane_o >> 1) * 4 + (idx_o >> 2);
        int j = (lane_o & 1) * 4 + (idx_o & 3);
        o_n[r] = n;
        o_j[r] = j;
        o_base[r] = (size_t)n * TB * HB + jbase + j;
    }
    const size_t NTH = (size_t)NB * TB * HB;

    // ---- step 0: h0 = initial + ih[:,0]
    for (int o = tid; o < NB * JB; o += RT) {
        int n = o & (NB - 1);
        int j = o >> 6;
        float v = initial[(size_t)n * HB + jbase + j] + g_ih[(size_t)n * TB * HB + jbase + j];
        g_h[0][jbase + j][n] = v;
        out[(size_t)n * TB * HB + jbase + j] = v;
        if (two) out[NTH + (size_t)n * TB * HB + jbase + j] = v;
    }
    grid_barrier(1u, bid, tid);

    // ---- steps 1..T-1
    for (int t = 1; t < TB; t++) {
        const float* hOld = &g_h[(t - 1) & 1][0][0];
        float* hNewCol = &g_h[t & 1][0][0];

        // prefetch u values early (latency hidden under the GEMM)
        float u0 = g_ih[o_base[0] + (size_t)(t - 1) * HB];
        float u1 = g_ih[o_base[1] + (size_t)(t - 1) * HB];

        // prefetch chunk 0
        {
            float* dst = hs;
            const float* src = hOld;
#pragma unroll
            for (int i = 0; i < (KC * NB / 4) / RT; i++) {
                int idx = tid + i * RT;
                cpasync16(dst + idx * 4, src + idx * 4);
            }
            cpasync_commit();
        }

        float a[16];
#pragma unroll
        for (int i = 0; i < 16; i++) a[i] = 0.f;

        for (int c = 0; c < NCHUNK; c++) {
            if (c + 1 < NCHUNK) {
                float* dst = hs + ((c + 1) & 1) * KC * NB;
                const float* src = hOld + (size_t)(c + 1) * KC * NB;
#pragma unroll
                for (int i = 0; i < (KC * NB / 4) / RT; i++) {
                    int idx = tid + i * RT;
                    cpasync16(dst + idx * 4, src + idx * 4);
                }
                cpasync_commit();
                cpasync_wait<1>();   // chunk c complete
            } else {
                cpasync_wait<0>();
            }
            __syncthreads();   // chunk c visible to everyone; safe to compute

            const float* hp = hs + (c & 1) * KC * NB + kw * NB;
            const float* wp = ws + (c * KC + kw) * JB;
#pragma unroll 8
            for (int k = 0; k < 32; k++) {
                float4 hv = *(const float4*)(hp + k * NB + n0);
                float4 wv = *(const float4*)(wp + k * JB + j0);
                a[0]  += hv.x * wv.x;  a[1]  += hv.x * wv.y;
                a[2]  += hv.x * wv.z;  a[3]  += hv.x * wv.w;
                a[4]  += hv.y * wv.x;  a[5]  += hv.y * wv.y;
                a[6]  += hv.y * wv.z;  a[7]  += hv.y * wv.w;
                a[8]  += hv.z * wv.x;  a[9]  += hv.z * wv.y;
                a[10] += hv.z * wv.z;  a[11] += hv.z * wv.w;
                a[12] += hv.w * wv.x;  a[13] += hv.w * wv.y;
                a[14] += hv.w * wv.z;  a[15] += hv.w * wv.w;
            }
            __syncthreads();   // done reading buf[c&1] before it is restaged next iter
        }

        // reduce 8 warp-partials per output (red aliases buf0; last compute used buf1)
#pragma unroll
        for (int idx = 0; idx < 16; idx++) red[warp * 512 + idx * 32 + lane] = a[idx];
        __syncthreads();

#pragma unroll
        for (int r = 0; r < 2; r++) {
            int o = ((tid & 31) << 4) | (r << 3) | (tid >> 5);
            int lane_o = o >> 4, idx_o = o & 15;
            float s = 0.f;
#pragma unroll
            for (int w = 0; w < 8; w++) s += red[w * 512 + idx_o * 32 + lane_o];
            float v = s + (r == 0 ? u0 : u1);
            hNewCol[(jbase + o_j[r]) * NB + o_n[r]] = v;
            size_t oaddr = o_base[r] + (size_t)t * HB;
            out[oaddr] = v;
            if (two) out[NTH + oaddr] = v;
        }

        if (t < TB - 1) grid_barrier((unsigned)(t + 1), bid, tid);
    }
}

// ---------------- launch ----------------
extern "C" void kernel_launch(void* const* d_in, const int* in_sizes, int n_in,
                              void* d_out, int out_size) {
    // defensive: map inputs by unique element counts
    const float* x = nullptr;        // 64*1024*88   = 5767168
    const float* initial = nullptr;  // 64*1024      = 65536
    const float* W_ih = nullptr;     // 1024*88      = 90112
    const float* b_ih = nullptr;     // 1024
    const float* W_hh = nullptr;     // 1024*1024    = 1048576
    for (int i = 0; i < n_in; i++) {
        switch (in_sizes[i]) {
            case 5767168: x = (const float*)d_in[i]; break;
            case 65536:   initial = (const float*)d_in[i]; break;
            case 90112:   W_ih = (const float*)d_in[i]; break;
            case 1024:    b_ih = (const float*)d_in[i]; break;
            case 1048576: W_hh = (const float*)d_in[i]; break;
            default: break;
        }
    }
    float* out = (float*)d_out;
    const long long NTH = (long long)NB * TB * HB;
    int two = ((long long)out_size >= 2 * NTH) ? 1 : 0;

    const int IH_SMEM = (IB * 64 + IB * 128) * 4;          // 67,584 B
    const int RNN_SMEM = (HB * JB + 2 * KC * NB) * 4;      // 163,840 B
    cudaFuncSetAttribute(ih_kernel, cudaFuncAttributeMaxDynamicSharedMemorySize, IH_SMEM);
    cudaFuncSetAttribute(rnn_kernel, cudaFuncAttributeMaxDynamicSharedMemorySize, RNN_SMEM);

    init_kernel<<<1, 128>>>();
    dim3 g1(HB / 128, (NB * TB) / 64);
    ih_kernel<<<g1, 256, IH_SMEM>>>(x, W_ih, b_ih);
    rnn_kernel<<<NCTA, RT, RNN_SMEM>>>(initial, W_hh, out, two);
}

// round 6
// speedup vs baseline: 2.9579x; 2.4557x over previous
#include <cuda_runtime.h>
#include <cuda_bf16.h>
#include <cstdint>

#define NB 64
#define TB 1024
#define IB 88
#define HB 1024

#define NCTA 128        // 4 batch-quarters x 32 col-groups
#define RT2 288         // 8 mma warps + 1 control warp

// smem byte offsets
#define SM_W    0        // W hi frag-packed 64KB, then W lo 64KB
#define SM_A    131072   // A hi 32KB, A lo 32KB
#define SM_RED  196608   // 4 n-tiles * 32 lanes * 4 floats = 2KB
#define SM_MBAR 198656   // 4 chunk mbarriers
#define SM_TOT  198720

// device scratch
__device__ __align__(256)  float g_ih[(size_t)NB * TB * HB];
// A-operand images, mma-fragment order: [buf][hi/lo][quarter][ktile 64][lane 32][reg 4] u32
__device__ __align__(1024) unsigned char g_ha[2][2][4][32768];
__device__ unsigned g_arrive, g_epoch;

__global__ void init_kernel() {
    if (threadIdx.x == 0) { g_arrive = 0u; g_epoch = 0u; }
}

// ---- ptx helpers (baseline sm_90/sm_80 PTX only; no 'a' features) ----
__device__ __forceinline__ void mbinit(uint32_t m, uint32_t c) {
    asm volatile("mbarrier.init.shared.b64 [%0], %1;" :: "r"(m), "r"(c) : "memory");
}
__device__ __forceinline__ void mbexpect(uint32_t m, uint32_t b) {
    asm volatile("mbarrier.arrive.expect_tx.shared.b64 _, [%0], %1;" :: "r"(m), "r"(b) : "memory");
}
__device__ __forceinline__ void mwait(uint32_t m, uint32_t par) {
    asm volatile(
        "{\n\t.reg .pred P;\n"
        "W%=:\n\t"
        "mbarrier.try_wait.parity.shared::cta.b64 P, [%0], %1, 0x989680;\n\t"
        "@P bra D%=;\n\t"
        "bra W%=;\n"
        "D%=:\n\t}" :: "r"(m), "r"(par) : "memory");
}
__device__ __forceinline__ void bulkcp8k(uint32_t dst, const void* src, uint32_t mbar) {
    asm volatile(
        "cp.async.bulk.shared::cluster.global.mbarrier::complete_tx::bytes [%0], [%1], %2, [%3];"
        :: "r"(dst), "l"(src), "r"(8192u), "r"(mbar) : "memory");
}
__device__ __forceinline__ void gbar(unsigned b) {
    unsigned old;
    asm volatile("atom.release.gpu.global.add.u32 %0, [%1], 1;"
                 : "=r"(old) : "l"(&g_arrive) : "memory");
    if (old + 1u == b * (unsigned)NCTA) {
        asm volatile("st.release.gpu.global.u32 [%0], %1;" :: "l"(&g_epoch), "r"(b) : "memory");
    } else {
        unsigned e;
        do {
            asm volatile("ld.acquire.gpu.global.u32 %0, [%1];" : "=r"(e) : "l"(&g_epoch) : "memory");
        } while (e < b);
    }
}
__device__ __forceinline__ void mma16816(float c[4], const uint32_t a[4], uint32_t b0, uint32_t b1) {
    asm volatile(
        "mma.sync.aligned.m16n8k16.row.col.f32.bf16.bf16.f32 "
        "{%0,%1,%2,%3}, {%4,%5,%6,%7}, {%8,%9}, {%0,%1,%2,%3};"
        : "+f"(c[0]), "+f"(c[1]), "+f"(c[2]), "+f"(c[3])
        : "r"(a[0]), "r"(a[1]), "r"(a[2]), "r"(a[3]), "r"(b0), "r"(b1));
}
__device__ __forceinline__ void split2(float a, float b, uint32_t& hi, uint32_t& lo) {
    __nv_bfloat16 ha = __float2bfloat16(a), hb = __float2bfloat16(b);
    __nv_bfloat16 la = __float2bfloat16(a - __bfloat162float(ha));
    __nv_bfloat16 lb = __float2bfloat16(b - __bfloat162float(hb));
    hi = (uint32_t)__bfloat16_as_ushort(ha) | ((uint32_t)__bfloat16_as_ushort(hb) << 16);
    lo = (uint32_t)__bfloat16_as_ushort(la) | ((uint32_t)__bfloat16_as_ushort(lb) << 16);
}

// ---- kernel 1: ih = x @ W_ih^T + b (fp32 SIMT) ----
__global__ __launch_bounds__(256) void ih_kernel(const float* __restrict__ x,
                                                 const float* __restrict__ W_ih,
                                                 const float* __restrict__ b_ih) {
    extern __shared__ float smf[];
    float* xs = smf;
    float* wt = smf + IB * 64;
    const int jb = blockIdx.x * 128, mb = blockIdx.y * 64, tid = threadIdx.x;
    for (int e = tid; e < 64 * IB; e += 256) {
        int m = e / IB, i = e - m * IB;
        xs[i * 64 + m] = x[(size_t)(mb + m) * IB + i];
    }
    for (int e = tid; e < 128 * IB; e += 256) {
        int j = e / IB, i = e - j * IB;
        wt[i * 128 + j] = W_ih[(size_t)(jb + j) * IB + i];
    }
    __syncthreads();
    const int jo = (tid & 15) * 8, mo = (tid >> 4) * 4;
    float acc[4][8];
#pragma unroll
    for (int jj = 0; jj < 8; jj++) {
        float b = b_ih[jb + jo + jj];
        acc[0][jj] = b; acc[1][jj] = b; acc[2][jj] = b; acc[3][jj] = b;
    }
#pragma unroll 4
    for (int i = 0; i < IB; i++) {
        float4 xv = *(const float4*)&xs[i * 64 + mo];
        float4 w0 = *(const float4*)&wt[i * 128 + jo];
        float4 w1 = *(const float4*)&wt[i * 128 + jo + 4];
        float xm[4] = {xv.x, xv.y, xv.z, xv.w};
#pragma unroll
        for (int mm = 0; mm < 4; mm++) {
            acc[mm][0] += xm[mm] * w0.x; acc[mm][1] += xm[mm] * w0.y;
            acc[mm][2] += xm[mm] * w0.z; acc[mm][3] += xm[mm] * w0.w;
            acc[mm][4] += xm[mm] * w1.x; acc[mm][5] += xm[mm] * w1.y;
            acc[mm][6] += xm[mm] * w1.z; acc[mm][7] += xm[mm] * w1.w;
        }
    }
#pragma unroll
    for (int mm = 0; mm < 4; mm++) {
        size_t row = (size_t)(mb + mo + mm) * HB + jb + jo;
        *(float4*)&g_ih[row]     = make_float4(acc[mm][0], acc[mm][1], acc[mm][2], acc[mm][3]);
        *(float4*)&g_ih[row + 4] = make_float4(acc[mm][4], acc[mm][5], acc[mm][6], acc[mm][7]);
    }
}

// ---- persistent split-bf16 HMMA recurrence ----
// CTA (q,g): batch rows q*16..+15, hidden cols g*32..+31.
// 8 mma warps: wid = nt(0..3) + 4*khalf ; warp does n-tile nt (8 cols), k-half khalf (512).
// warp 8 = control: grid barrier + bulk-copy A images.
__global__ __launch_bounds__(RT2, 1)
void rnn_kernel(const float* __restrict__ initial, const float* __restrict__ W_hh,
                float* __restrict__ out, int two) {
    extern __shared__ __align__(1024) unsigned char sm[];
    const uint32_t smb = (uint32_t)__cvta_generic_to_shared(sm);
    const int tid = threadIdx.x, wid = tid >> 5, lane = tid & 31;
    const int bid = blockIdx.x;
    const int q = bid >> 5, g = bid & 31, jb = g * 32;
    float* red = (float*)(sm + SM_RED);
    const uint32_t mb0 = smb + SM_MBAR;
    const size_t NTH = (size_t)NB * TB * HB;

    if (tid == 0)
        for (int ch = 0; ch < 4; ch++) mbinit(mb0 + ch * 8, 1);

    // stage W slice, fragment-packed: element (n local col 0..31, k 0..1023)
    for (int e = tid; e < 32 * HB; e += RT2) {
        int n = e >> 10, k = e & (HB - 1);
        float w = W_hh[(size_t)(jb + n) * HB + k];
        __nv_bfloat16 hv = __float2bfloat16(w);
        __nv_bfloat16 lv = __float2bfloat16(w - __bfloat162float(hv));
        int nt = n >> 3, nn = n & 7, kt = k >> 4, kk = k & 15;
        int lf = nn * 4 + ((kk >> 1) & 3);
        uint32_t off = (uint32_t)(((nt * 64 + kt) * 32 + lf) * 8 + (kk >> 3) * 4 + (kk & 1) * 2);
        *(unsigned short*)(sm + SM_W + off)         = __bfloat16_as_ushort(hv);
        *(unsigned short*)(sm + SM_W + 65536 + off) = __bfloat16_as_ushort(lv);
    }

    // ---- step 0: h0 = initial + ih[:,0]; emit out + A image buf0 ----
    for (int e = tid; e < 512; e += RT2) {
        int row = e >> 5, j = e & 31, jg = jb + j, n0 = q * 16 + row;
        float v = initial[(size_t)n0 * HB + jg] + g_ih[(size_t)n0 * TB * HB + jg];
        out[(size_t)n0 * TB * HB + jg] = v;
        if (two) out[NTH + (size_t)n0 * TB * HB + jg] = v;
        __nv_bfloat16 hv = __float2bfloat16(v);
        __nv_bfloat16 lv = __float2bfloat16(v - __bfloat162float(hv));
        int kt = jg >> 4, kk = jg & 15;
        int la = ((row & 7) << 2) | ((kk >> 1) & 3);
        int rg = ((row >> 3) & 1) | ((kk >> 3) << 1);
        uint32_t off = (uint32_t)(kt * 512 + la * 16 + rg * 4 + (kk & 1) * 2);
        *(unsigned short*)(&g_ha[0][0][q][off]) = __bfloat16_as_ushort(hv);
        *(unsigned short*)(&g_ha[0][1][q][off]) = __bfloat16_as_ushort(lv);
    }
    asm volatile("fence.proxy.async;" ::: "memory");
    __syncthreads();

    const int nt = wid & 3, kh = wid >> 2;   // for wid<8

    for (int t = 1; t < TB; t++) {
        const uint32_t par = (uint32_t)((t - 1) & 1);
        if (wid == 8) {
            // -------- control warp --------
            if (lane == 0) {
                asm volatile("fence.proxy.async;" ::: "memory");
                gbar((unsigned)t);
                const unsigned char* hs = &g_ha[(t - 1) & 1][0][q][0];
                const unsigned char* ls = &g_ha[(t - 1) & 1][1][q][0];
#pragma unroll
                for (int ch = 0; ch < 4; ch++) {
                    mbexpect(mb0 + ch * 8, 16384u);
                    bulkcp8k(smb + SM_A + ch * 8192,         hs + ch * 8192, mb0 + ch * 8);
                    bulkcp8k(smb + SM_A + 32768 + ch * 8192, ls + ch * 8192, mb0 + ch * 8);
                }
            }
            __syncthreads();   // matches reduce-sync
            __syncthreads();   // matches end-sync
        } else {
            // -------- mma warps --------
            float2 u0, u1;
            if (kh == 0) {     // epilogue owners prefetch u early
                int row = lane >> 2, j0 = jb + nt * 8 + 2 * (lane & 3);
                const float* up = g_ih + ((size_t)(q * 16 + row) * TB + (t - 1)) * HB + j0;
                u0 = *(const float2*)up;
                u1 = *(const float2*)(up + (size_t)8 * TB * HB);
            }
            float c[4] = {0.f, 0.f, 0.f, 0.f};
#pragma unroll
            for (int chh = 0; chh < 2; chh++) {
                int ch = 2 * kh + chh;
                mwait(mb0 + ch * 8, par);
                uint32_t aoff = smb + SM_A + (uint32_t)(ch * 16) * 512 + lane * 16;
                uint32_t boff = smb + SM_W + (uint32_t)((nt * 64 + ch * 16) * 32 + lane) * 8;
#pragma unroll
                for (int kt = 0; kt < 16; kt++) {
                    uint32_t ah[4], al[4], bh0, bh1, bl0, bl1;
                    asm volatile("ld.shared.v4.u32 {%0,%1,%2,%3}, [%4];"
                        : "=r"(ah[0]), "=r"(ah[1]), "=r"(ah[2]), "=r"(ah[3]) : "r"(aoff));
                    asm volatile("ld.shared.v4.u32 {%0,%1,%2,%3}, [%4];"
                        : "=r"(al[0]), "=r"(al[1]), "=r"(al[2]), "=r"(al[3]) : "r"(aoff + 32768u));
                    asm volatile("ld.shared.v2.u32 {%0,%1}, [%2];"
                        : "=r"(bh0), "=r"(bh1) : "r"(boff));
                    asm volatile("ld.shared.v2.u32 {%0,%1}, [%2];"
                        : "=r"(bl0), "=r"(bl1) : "r"(boff + 65536u));
                    mma16816(c, ah, bh0, bh1);   // hi*hi
                    mma16816(c, al, bh0, bh1);   // lo*hi
                    mma16816(c, ah, bl0, bl1);   // hi*lo
                    aoff += 512u;
                    boff += 256u;
                }
            }
            if (kh == 1)
                *(float4*)&red[(nt * 32 + lane) * 4] = make_float4(c[0], c[1], c[2], c[3]);
            __syncthreads();   // reduce-sync
            if (kh == 0) {
                float4 r = *(const float4*)&red[(nt * 32 + lane) * 4];
                int row = lane >> 2, j0 = jb + nt * 8 + 2 * (lane & 3);
                int n0 = q * 16 + row;
                float v00 = c[0] + r.x + u0.x, v01 = c[1] + r.y + u0.y;
                float v10 = c[2] + r.z + u1.x, v11 = c[3] + r.w + u1.y;

                float* ob = out + ((size_t)n0 * TB + t) * HB + j0;
                *(float2*)ob = make_float2(v00, v01);
                *(float2*)(ob + (size_t)8 * TB * HB) = make_float2(v10, v11);
                if (two) {
                    *(float2*)(ob + NTH) = make_float2(v00, v01);
                    *(float2*)(ob + NTH + (size_t)8 * TB * HB) = make_float2(v10, v11);
                }
                // A image for next step (fragment-packed): rows row & row+8, cols j0,j0+1
                int kt = j0 >> 4, kk = j0 & 15;           // kk even
                int la = (row << 2) | ((kk >> 1) & 3);    // row in 0..7
                int rgH = (kk >> 3) << 1;
                uint32_t base = (uint32_t)(kt * 512 + la * 16);
                unsigned char* hiImg = &g_ha[t & 1][0][q][0];
                unsigned char* loImg = &g_ha[t & 1][1][q][0];
                uint32_t h01, l01, h23, l23;
                split2(v00, v01, h01, l01);
                split2(v10, v11, h23, l23);
                *(uint32_t*)(hiImg + base + rgH * 4)       = h01;
                *(uint32_t*)(hiImg + base + (rgH | 1) * 4) = h23;
                *(uint32_t*)(loImg + base + rgH * 4)       = l01;
                *(uint32_t*)(loImg + base + (rgH | 1) * 4) = l23;
                asm volatile("fence.proxy.async;" ::: "memory");
            }
            __syncthreads();   // end-sync
        }
    }
}

// ---- launch ----
extern "C" void kernel_launch(void* const* d_in, const int* in_sizes, int n_in,
                              void* d_out, int out_size) {
    const float *x = nullptr, *initial = nullptr, *W_ih = nullptr, *b_ih = nullptr, *W_hh = nullptr;
    for (int i = 0; i < n_in; i++) {
        switch (in_sizes[i]) {
            case 5767168: x = (const float*)d_in[i]; break;
            case 65536:   initial = (const float*)d_in[i]; break;
            case 90112:   W_ih = (const float*)d_in[i]; break;
            case 1024:    b_ih = (const float*)d_in[i]; break;
            case 1048576: W_hh = (const float*)d_in[i]; break;
            default: break;
        }
    }
    float* out = (float*)d_out;
    const long long NTH = (long long)NB * TB * HB;
    int two = ((long long)out_size >= 2 * NTH) ? 1 : 0;

    const int IH_SMEM = (IB * 64 + IB * 128) * 4;
    cudaFuncSetAttribute(ih_kernel, cudaFuncAttributeMaxDynamicSharedMemorySize, IH_SMEM);
    cudaFuncSetAttribute(rnn_kernel, cudaFuncAttributeMaxDynamicSharedMemorySize, SM_TOT);

    init_kernel<<<1, 32>>>();
    dim3 g1(HB / 128, (NB * TB) / 64);
    ih_kernel<<<g1, 256, IH_SMEM>>>(x, W_ih, b_ih);
    rnn_kernel<<<NCTA, RT2, SM_TOT>>>(initial, W_hh, out, two);
}

// round 7
// speedup vs baseline: 3.5927x; 1.2146x over previous
#include <cuda_runtime.h>
#include <cuda_bf16.h>
#include <cstdint>

#define NB 64
#define TB 1024
#define IB 88
#define HB 1024

#define NCTA 128        // 4 batch-quarters x 32 col-groups
#define RT2 288         // 8 mma warps + 1 control warp

// smem byte offsets
#define SM_W    0        // W hi frag-packed 64KB, then W lo 64KB
#define SM_A    131072   // A hi 32KB, A lo 32KB
#define SM_RED  196608   // 8 warps * 512 floats = 16KB
#define SM_MBAR 212992   // 4 chunk mbarriers
#define SM_TOT  213120

// device scratch
__device__ __align__(256)  float g_ih[(size_t)NB * TB * HB];
// A-operand images, mma-fragment order: [buf][hi/lo][quarter][ktile 64][lane 32][reg 4] u32
__device__ __align__(1024) unsigned char g_ha[2][2][4][32768];
__device__ unsigned g_arrive, g_epoch;

__global__ void init_kernel() {
    if (threadIdx.x == 0) { g_arrive = 0u; g_epoch = 0u; }
}

// ---- ptx helpers (baseline PTX only; no 'a' features) ----
__device__ __forceinline__ void mbinit(uint32_t m, uint32_t c) {
    asm volatile("mbarrier.init.shared.b64 [%0], %1;" :: "r"(m), "r"(c) : "memory");
}
__device__ __forceinline__ void mbexpect(uint32_t m, uint32_t b) {
    asm volatile("mbarrier.arrive.expect_tx.shared.b64 _, [%0], %1;" :: "r"(m), "r"(b) : "memory");
}
__device__ __forceinline__ void mwait(uint32_t m, uint32_t par) {
    asm volatile(
        "{\n\t.reg .pred P;\n"
        "W%=:\n\t"
        "mbarrier.try_wait.parity.shared::cta.b64 P, [%0], %1, 0x989680;\n\t"
        "@P bra D%=;\n\t"
        "bra W%=;\n"
        "D%=:\n\t}" :: "r"(m), "r"(par) : "memory");
}
__device__ __forceinline__ void bulkcp8k(uint32_t dst, const void* src, uint32_t mbar) {
    asm volatile(
        "cp.async.bulk.shared::cluster.global.mbarrier::complete_tx::bytes [%0], [%1], %2, [%3];"
        :: "r"(dst), "l"(src), "r"(8192u), "r"(mbar) : "memory");
}
__device__ __forceinline__ void gbar(unsigned b) {
    unsigned old;
    asm volatile("atom.release.gpu.global.add.u32 %0, [%1], 1;"
                 : "=r"(old) : "l"(&g_arrive) : "memory");
    if (old + 1u == b * (unsigned)NCTA) {
        asm volatile("st.release.gpu.global.u32 [%0], %1;" :: "l"(&g_epoch), "r"(b) : "memory");
    } else {
        unsigned e;
        do {
            asm volatile("ld.acquire.gpu.global.u32 %0, [%1];" : "=r"(e) : "l"(&g_epoch) : "memory");
        } while (e < b);
    }
}
__device__ __forceinline__ void mma16816(float c[4], const uint32_t a[4], uint32_t b0, uint32_t b1) {
    asm volatile(
        "mma.sync.aligned.m16n8k16.row.col.f32.bf16.bf16.f32 "
        "{%0,%1,%2,%3}, {%4,%5,%6,%7}, {%8,%9}, {%0,%1,%2,%3};"
        : "+f"(c[0]), "+f"(c[1]), "+f"(c[2]), "+f"(c[3])
        : "r"(a[0]), "r"(a[1]), "r"(a[2]), "r"(a[3]), "r"(b0), "r"(b1));
}
__device__ __forceinline__ void split2(float a, float b, uint32_t& hi, uint32_t& lo) {
    __nv_bfloat16 ha = __float2bfloat16(a), hb = __float2bfloat16(b);
    __nv_bfloat16 la = __float2bfloat16(a - __bfloat162float(ha));
    __nv_bfloat16 lb = __float2bfloat16(b - __bfloat162float(hb));
    hi = (uint32_t)__bfloat16_as_ushort(ha) | ((uint32_t)__bfloat16_as_ushort(hb) << 16);
    lo = (uint32_t)__bfloat16_as_ushort(la) | ((uint32_t)__bfloat16_as_ushort(lb) << 16);
}

// ---- kernel 1: ih = x @ W_ih^T + b (fp32 SIMT) ----
__global__ __launch_bounds__(256) void ih_kernel(const float* __restrict__ x,
                                                 const float* __restrict__ W_ih,
                                                 const float* __restrict__ b_ih) {
    extern __shared__ float smf[];
    float* xs = smf;
    float* wt = smf + IB * 64;
    const int jb = blockIdx.x * 128, mb = blockIdx.y * 64, tid = threadIdx.x;
    for (int e = tid; e < 64 * IB; e += 256) {
        int m = e / IB, i = e - m * IB;
        xs[i * 64 + m] = x[(size_t)(mb + m) * IB + i];
    }
    for (int e = tid; e < 128 * IB; e += 256) {
        int j = e / IB, i = e - j * IB;
        wt[i * 128 + j] = W_ih[(size_t)(jb + j) * IB + i];
    }
    __syncthreads();
    const int jo = (tid & 15) * 8, mo = (tid >> 4) * 4;
    float acc[4][8];
#pragma unroll
    for (int jj = 0; jj < 8; jj++) {
        float b = b_ih[jb + jo + jj];
        acc[0][jj] = b; acc[1][jj] = b; acc[2][jj] = b; acc[3][jj] = b;
    }
#pragma unroll 4
    for (int i = 0; i < IB; i++) {
        float4 xv = *(const float4*)&xs[i * 64 + mo];
        float4 w0 = *(const float4*)&wt[i * 128 + jo];
        float4 w1 = *(const float4*)&wt[i * 128 + jo + 4];
        float xm[4] = {xv.x, xv.y, xv.z, xv.w};
#pragma unroll
        for (int mm = 0; mm < 4; mm++) {
            acc[mm][0] += xm[mm] * w0.x; acc[mm][1] += xm[mm] * w0.y;
            acc[mm][2] += xm[mm] * w0.z; acc[mm][3] += xm[mm] * w0.w;
            acc[mm][4] += xm[mm] * w1.x; acc[mm][5] += xm[mm] * w1.y;
            acc[mm][6] += xm[mm] * w1.z; acc[mm][7] += xm[mm] * w1.w;
        }
    }
#pragma unroll
    for (int mm = 0; mm < 4; mm++) {
        size_t row = (size_t)(mb + mo + mm) * HB + jb + jo;
        *(float4*)&g_ih[row]     = make_float4(acc[mm][0], acc[mm][1], acc[mm][2], acc[mm][3]);
        *(float4*)&g_ih[row + 4] = make_float4(acc[mm][4], acc[mm][5], acc[mm][6], acc[mm][7]);
    }
}

// ---- persistent split-bf16 HMMA recurrence ----
// CTA (q,g): batch rows q*16..+15, hidden cols g*32..+31.
// 8 mma warps: warp w owns k in [w*128, w*128+128) (8 ktiles) x ALL 4 n-tiles.
// B-hi lives in registers (loaded once); B-lo read from smem; A streamed per step.
// warp 8 = control: grid barrier + bulk-copy A images.
__global__ __launch_bounds__(RT2, 1)
void rnn_kernel(const float* __restrict__ initial, const float* __restrict__ W_hh,
                float* __restrict__ out, int two) {
    extern __shared__ __align__(1024) unsigned char sm[];
    const uint32_t smb = (uint32_t)__cvta_generic_to_shared(sm);
    const int tid = threadIdx.x, wid = tid >> 5, lane = tid & 31;
    const int bid = blockIdx.x;
    const int q = bid >> 5, g = bid & 31, jb = g * 32;
    float* red = (float*)(sm + SM_RED);
    const uint32_t mb0 = smb + SM_MBAR;
    const size_t NTH = (size_t)NB * TB * HB;

    if (tid == 0)
        for (int ch = 0; ch < 4; ch++) mbinit(mb0 + ch * 8, 1);

    // stage W slice, fragment-packed (hi at SM_W, lo at +64KB)
    for (int e = tid; e < 32 * HB; e += RT2) {
        int n = e >> 10, k = e & (HB - 1);
        float w = W_hh[(size_t)(jb + n) * HB + k];
        __nv_bfloat16 hv = __float2bfloat16(w);
        __nv_bfloat16 lv = __float2bfloat16(w - __bfloat162float(hv));
        int nt = n >> 3, nn = n & 7, kt = k >> 4, kk = k & 15;
        int lf = nn * 4 + ((kk >> 1) & 3);
        uint32_t off = (uint32_t)(((nt * 64 + kt) * 32 + lf) * 8 + (kk >> 3) * 4 + (kk & 1) * 2);
        *(unsigned short*)(sm + SM_W + off)         = __bfloat16_as_ushort(hv);
        *(unsigned short*)(sm + SM_W + 65536 + off) = __bfloat16_as_ushort(lv);
    }

    // ---- step 0: h0 = initial + ih[:,0]; emit out + A image buf0 ----
    for (int e = tid; e < 512; e += RT2) {
        int row = e >> 5, j = e & 31, jg = jb + j, n0 = q * 16 + row;
        float v = initial[(size_t)n0 * HB + jg] + g_ih[(size_t)n0 * TB * HB + jg];
        out[(size_t)n0 * TB * HB + jg] = v;
        if (two) out[NTH + (size_t)n0 * TB * HB + jg] = v;
        __nv_bfloat16 hv = __float2bfloat16(v);
        __nv_bfloat16 lv = __float2bfloat16(v - __bfloat162float(hv));
        int kt = jg >> 4, kk = jg & 15;
        int la = ((row & 7) << 2) | ((kk >> 1) & 3);
        int rg = ((row >> 3) & 1) | ((kk >> 3) << 1);
        uint32_t off = (uint32_t)(kt * 512 + la * 16 + rg * 4 + (kk & 1) * 2);
        *(unsigned short*)(&g_ha[0][0][q][off]) = __bfloat16_as_ushort(hv);
        *(unsigned short*)(&g_ha[0][1][q][off]) = __bfloat16_as_ushort(lv);
    }
    asm volatile("fence.proxy.async;" ::: "memory");
    __syncthreads();

    // ---- preload B-hi fragments into registers (reused for all 1023 steps) ----
    uint32_t bh[4][8][2];
    if (wid < 8) {
#pragma unroll
        for (int nt = 0; nt < 4; nt++)
#pragma unroll
            for (int kt = 0; kt < 8; kt++) {
                uint32_t boff = smb + SM_W +
                    (uint32_t)(((nt * 64 + wid * 8 + kt) * 32 + lane) * 8);
                asm volatile("ld.shared.v2.u32 {%0,%1}, [%2];"
                    : "=r"(bh[nt][kt][0]), "=r"(bh[nt][kt][1]) : "r"(boff));
            }
    }

    // epilogue constants: thread j (0..255) handles outputs o = 2j, 2j+1
    const int ent = tid >> 6;
    const int elane = (tid >> 1) & 31;
    const int eip = tid & 1;
    const int erow = (elane >> 2) + eip * 8;
    const int ecol = ent * 8 + (elane & 3) * 2;
    const int en0 = q * 16 + erow;
    const int ejg = jb + ecol;
    const int ebase = ent * 128 + elane * 4 + 2 * eip;
    // image offsets for (erow, ecol pair)
    const int ikt = ejg >> 4, ikk = ejg & 15;
    const int ila = ((erow & 7) << 2) | ((ikk >> 1) & 3);
    const int irg = ((erow >> 3) & 1) | ((ikk >> 3) << 1);
    const uint32_t ioff = (uint32_t)(ikt * 512 + ila * 16 + irg * 4);

    for (int t = 1; t < TB; t++) {
        const uint32_t par = (uint32_t)((t - 1) & 1);
        if (wid == 8) {
            // -------- control warp --------
            if (lane == 0) {
                asm volatile("fence.proxy.async;" ::: "memory");
                gbar((unsigned)t);
                const unsigned char* hs = &g_ha[(t - 1) & 1][0][q][0];
                const unsigned char* ls = &g_ha[(t - 1) & 1][1][q][0];
#pragma unroll
                for (int ch = 0; ch < 4; ch++) {
                    mbexpect(mb0 + ch * 8, 16384u);
                    bulkcp8k(smb + SM_A + ch * 8192,         hs + ch * 8192, mb0 + ch * 8);
                    bulkcp8k(smb + SM_A + 32768 + ch * 8192, ls + ch * 8192, mb0 + ch * 8);
                }
            }
            __syncthreads();   // reduce-sync
            __syncthreads();   // end-sync
        } else {
            // -------- mma warps --------
            // prefetch u early (independent of mbarrier)
            float2 u = *(const float2*)(g_ih + ((size_t)en0 * TB + (t - 1)) * HB + ejg);

            float c[4][4];
#pragma unroll
            for (int nt = 0; nt < 4; nt++) { c[nt][0]=0.f; c[nt][1]=0.f; c[nt][2]=0.f; c[nt][3]=0.f; }

            mwait(mb0 + (wid >> 1) * 8, par);
            uint32_t aoff = smb + SM_A + (uint32_t)(wid * 8) * 512 + lane * 16;
#pragma unroll
            for (int kt = 0; kt < 8; kt++) {
                uint32_t ah[4], al[4];
                asm volatile("ld.shared.v4.u32 {%0,%1,%2,%3}, [%4];"
                    : "=r"(ah[0]), "=r"(ah[1]), "=r"(ah[2]), "=r"(ah[3]) : "r"(aoff));
                asm volatile("ld.shared.v4.u32 {%0,%1,%2,%3}, [%4];"
                    : "=r"(al[0]), "=r"(al[1]), "=r"(al[2]), "=r"(al[3]) : "r"(aoff + 32768u));
#pragma unroll
                for (int nt = 0; nt < 4; nt++) {
                    uint32_t bl0, bl1;
                    uint32_t bloff = smb + SM_W + 65536u +
                        (uint32_t)(((nt * 64 + wid * 8 + kt) * 32 + lane) * 8);
                    asm volatile("ld.shared.v2.u32 {%0,%1}, [%2];"
                        : "=r"(bl0), "=r"(bl1) : "r"(bloff));
                    mma16816(c[nt], ah, bh[nt][kt][0], bh[nt][kt][1]);  // hi*hi
                    mma16816(c[nt], al, bh[nt][kt][0], bh[nt][kt][1]);  // lo*hi
                    mma16816(c[nt], ah, bl0, bl1);                      // hi*lo
                }
                aoff += 512u;
            }
            // write partials: red[wid*512 + nt*128 + lane*4 + i]
            {
                float* rp = red + wid * 512 + lane * 4;
#pragma unroll
                for (int nt = 0; nt < 4; nt++)
                    *(float4*)(rp + nt * 128) = make_float4(c[nt][0], c[nt][1], c[nt][2], c[nt][3]);
            }
            __syncthreads();   // reduce-sync

            // epilogue: 256 threads, 2 outputs each
            float s0 = 0.f, s1 = 0.f;
#pragma unroll
            for (int w = 0; w < 8; w++) {
                s0 += red[w * 512 + ebase];
                s1 += red[w * 512 + ebase + 1];
            }
            float v0 = s0 + u.x, v1 = s1 + u.y;

            float* ob = out + ((size_t)en0 * TB + t) * HB + ejg;
            *(float2*)ob = make_float2(v0, v1);
            if (two) *(float2*)(ob + NTH) = make_float2(v0, v1);

            uint32_t hp, lp;
            split2(v0, v1, hp, lp);
            *(uint32_t*)(&g_ha[t & 1][0][q][ioff]) = hp;
            *(uint32_t*)(&g_ha[t & 1][1][q][ioff]) = lp;
            asm volatile("fence.proxy.async;" ::: "memory");
            __syncthreads();   // end-sync
        }
    }
}

// ---- launch ----
extern "C" void kernel_launch(void* const* d_in, const int* in_sizes, int n_in,
                              void* d_out, int out_size) {
    const float *x = nullptr, *initial = nullptr, *W_ih = nullptr, *b_ih = nullptr, *W_hh = nullptr;
    for (int i = 0; i < n_in; i++) {
        switch (in_sizes[i]) {
            case 5767168: x = (const float*)d_in[i]; break;
            case 65536:   initial = (const float*)d_in[i]; break;
            case 90112:   W_ih = (const float*)d_in[i]; break;
            case 1024:    b_ih = (const float*)d_in[i]; break;
            case 1048576: W_hh = (const float*)d_in[i]; break;
            default: break;
        }
    }
    float* out = (float*)d_out;
    const long long NTH = (long long)NB * TB * HB;
    int two = ((long long)out_size >= 2 * NTH) ? 1 : 0;

    const int IH_SMEM = (IB * 64 + IB * 128) * 4;
    cudaFuncSetAttribute(ih_kernel, cudaFuncAttributeMaxDynamicSharedMemorySize, IH_SMEM);
    cudaFuncSetAttribute(rnn_kernel, cudaFuncAttributeMaxDynamicSharedMemorySize, SM_TOT);

    init_kernel<<<1, 32>>>();
    dim3 g1(HB / 128, (NB * TB) / 64);
    ih_kernel<<<g1, 256, IH_SMEM>>>(x, W_ih, b_ih);
    rnn_kernel<<<NCTA, RT2, SM_TOT>>>(initial, W_hh, out, two);
}